// round 11
// baseline (speedup 1.0000x reference)
#include <cuda_runtime.h>
#include <math.h>

#define NA 2304
#define N_PROP 2000
#define FC1_K 3136
#define WMAX 36

#define OFF_RPN_LOGITS   0
#define OFF_RPN_DELTAS   4608
#define OFF_PROPOSALS    13824
#define OFF_ANCHORS      21824
#define OFF_RCNN_LOGITS  31040
#define OFF_RCNN_DELTAS  35040
#define OFF_RCNN_MASKS   43040
#define OFF_FINAL_DETS   435040
#define OFF_FINAL_MASKS  443040
#define OFF_FINAL_SCORES 835040
#define OFF_KEEP2        837040

// ---------------- scratch ----------------
__device__ __align__(16) float g_feat[64 * 256];
__device__ __align__(16) float g_h[64 * 256];
__device__ __align__(16) float g_scores[NA];
__device__ __align__(16) float g_boxes[NA * 4];
__device__ __align__(16) float g_sbx[NA * 4];
__device__ float g_sar[NA];
__device__ int   g_sord[NA];
__device__ unsigned long long g_mask[NA * WMAX];
__device__ __align__(16) float g_prop[N_PROP * 4];
__device__ unsigned char g_valid[N_PROP];
__device__ __align__(16) float g_pooled[N_PROP * FC1_K];
__device__ __align__(16) float g_h1[N_PROP * 512];
__device__ __align__(16) float g_h2[N_PROP * 512];
__device__ __align__(16) float g_dets[N_PROP * 4];
__device__ __align__(16) float g_sdets[N_PROP * 4];
__device__ float g_dscores[N_PROP];
__device__ float g_s2[N_PROP];
__device__ int   g_order2[N_PROP];
__device__ unsigned char g_keep2[N_PROP];
__device__ __align__(16) unsigned long long g_wpack[32 * 576];  // packed co-pair mask weights

// ---------------- f32x2 helpers ----------------
__device__ __forceinline__ void fma2(unsigned long long& d, unsigned long long a,
                                     unsigned long long b) {
    asm("fma.rn.f32x2 %0, %1, %2, %0;" : "+l"(d) : "l"(a), "l"(b));
}
__device__ __forceinline__ unsigned long long dup2(float x) {
    unsigned long long r;
    asm("mov.b64 %0, {%1, %1};" : "=l"(r) : "f"(x));
    return r;
}
__device__ __forceinline__ unsigned long long pk2(float lo, float hi) {
    unsigned long long r;
    asm("mov.b64 %0, {%1, %2};" : "=l"(r) : "f"(lo), "f"(hi));
    return r;
}
__device__ __forceinline__ void upk2(unsigned long long v, float& lo, float& hi) {
    asm("mov.b64 {%0, %1}, %2;" : "=f"(lo), "=f"(hi) : "l"(v));
}

// ---------------- backbone ----------------
__global__ void k_backbone(const float* __restrict__ x, const float* __restrict__ w,
                           const float* __restrict__ b) {
    __shared__ float patch[768];
    int pos = blockIdx.x, py = pos >> 4, px = pos & 15;
    int t = threadIdx.x;  // 64
    for (int i = t; i < 768; i += 64) {
        int ci = i >> 8, rem = i & 255, ky = rem >> 4, kx = rem & 15;
        patch[i] = x[ci * 65536 + (py * 16 + ky) * 256 + (px * 16 + kx)];
    }
    __syncthreads();
    const float* wc = w + t * 768;
    float acc = b[t];
#pragma unroll 8
    for (int i = 0; i < 768; i++) acc += patch[i] * __ldg(&wc[i]);
    g_feat[t * 256 + pos] = fmaxf(acc, 0.f);
}

// ---------------- RPN 3x3 SAME conv ----------------
__global__ void k_rpnconv(const float* __restrict__ w, const float* __restrict__ b) {
    __shared__ float ws[576];
    int c = blockIdx.x, t = threadIdx.x;  // 256
    for (int i = t; i < 576; i += 256) ws[i] = w[c * 576 + i];
    __syncthreads();
    int y = t >> 4, x = t & 15;
    float acc = b[c];
    for (int ci = 0; ci < 64; ci++) {
        const float* f = g_feat + ci * 256;
#pragma unroll
        for (int ky = 0; ky < 3; ky++) {
            int yy = y + ky - 1;
            if (yy < 0 || yy > 15) continue;
#pragma unroll
            for (int kx = 0; kx < 3; kx++) {
                int xx = x + kx - 1;
                if (xx < 0 || xx > 15) continue;
                acc += __ldg(&f[yy * 16 + xx]) * ws[ci * 9 + ky * 3 + kx];
            }
        }
    }
    g_h[c * 256 + t] = fmaxf(acc, 0.f);
}

// ---------------- RPN heads + anchors + decode + clip ----------------
__global__ void k_rpnhead(const float* __restrict__ wcls, const float* __restrict__ bcls,
                          const float* __restrict__ wbox, const float* __restrict__ bbox,
                          float* __restrict__ out) {
    __shared__ float hv[64], lg[18], dl[36];
    int pos = blockIdx.x, y = pos >> 4, x = pos & 15;
    int t = threadIdx.x;  // 64
    hv[t] = g_h[t * 256 + pos];
    __syncthreads();
    if (t < 54) {
        int a = t / 6, j = t % 6;
        if (j < 2) {
            int o = a * 2 + j;
            float acc = bcls[o];
            const float* wr = wcls + o * 64;
            for (int ci = 0; ci < 64; ci++) acc += hv[ci] * wr[ci];
            lg[o] = acc;
            out[OFF_RPN_LOGITS + (pos * 9 + a) * 2 + j] = acc;
        } else {
            int o = a * 4 + (j - 2);
            float acc = bbox[o];
            const float* wr = wbox + o * 64;
            for (int ci = 0; ci < 64; ci++) acc += hv[ci] * wr[ci];
            dl[o] = acc;
            out[OFF_RPN_DELTAS + (pos * 9 + a) * 4 + (j - 2)] = acc;
        }
    }
    __syncthreads();
    if (t < 9) {
        int a = t;
        float l0 = lg[a * 2], l1 = lg[a * 2 + 1];
        float mx = fmaxf(l0, l1);
        float e0 = expf(l0 - mx), e1 = expf(l1 - mx);
        float sc = e1 / (e0 + e1);
        const float scl[3] = {32.f, 64.f, 128.f};
        const float rat[3] = {0.5f, 1.f, 2.f};
        float s = scl[a / 3], r = rat[a % 3];
        float ws = s * sqrtf(r), hs = s / sqrtf(r);
        float cx = ((float)x + 0.5f) * 16.f, cy = ((float)y + 0.5f) * 16.f;
        float a0 = cx - ws * 0.5f, a1 = cy - hs * 0.5f;
        float a2 = cx + ws * 0.5f, a3 = cy + hs * 0.5f;
        int ai = pos * 9 + a;
        out[OFF_ANCHORS + ai * 4 + 0] = a0;
        out[OFF_ANCHORS + ai * 4 + 1] = a1;
        out[OFF_ANCHORS + ai * 4 + 2] = a2;
        out[OFF_ANCHORS + ai * 4 + 3] = a3;
        float w = a2 - a0, h = a3 - a1;
        float ccx = a0 + 0.5f * w, ccy = a1 + 0.5f * h;
        float ncx = ccx + dl[a * 4 + 0] * w, ncy = ccy + dl[a * 4 + 1] * h;
        float nw = w * expf(dl[a * 4 + 2]), nh = h * expf(dl[a * 4 + 3]);
        g_scores[ai] = sc;
        g_boxes[ai * 4 + 0] = fminf(fmaxf(ncx - 0.5f * nw, 0.f), 255.f);
        g_boxes[ai * 4 + 1] = fminf(fmaxf(ncy - 0.5f * nh, 0.f), 255.f);
        g_boxes[ai * 4 + 2] = fminf(fmaxf(ncx + 0.5f * nw, 0.f), 255.f);
        g_boxes[ai * 4 + 3] = fminf(fmaxf(ncy + 0.5f * nh, 0.f), 255.f);
    }
}

// ---------------- S1: stable descending sort ----------------
__device__ __forceinline__ unsigned int fmap(float s) {
    unsigned int u = __float_as_uint(s);
    return (u & 0x80000000u) ? ~u : (u | 0x80000000u);
}

template <int P>
__global__ void __launch_bounds__(1024, 1) k_sort(int stage) {
    __shared__ unsigned long long keys[P];
    const int n = stage ? N_PROP : NA;
    const float* scores = stage ? g_s2 : g_scores;
    const float* boxes = stage ? g_dets : g_boxes;
    int t = threadIdx.x;  // 1024
#pragma unroll
    for (int s = 0; s < P / 1024; s++) {
        int i = t + s * 1024;
        unsigned long long k = 0ull;
        if (i < n)
            k = ((unsigned long long)fmap(scores[i]) << 32) |
                (unsigned long long)(0xFFFFFFFFu - (unsigned)i);
        keys[i] = k;
    }
    __syncthreads();
    for (int k = 2; k <= P; k <<= 1) {
        for (int j = k >> 1; j > 0; j >>= 1) {
#pragma unroll
            for (int s = 0; s < P / 1024; s++) {
                int i = t + s * 1024;
                int ixj = i ^ j;
                if (ixj > i) {
                    bool desc = ((i & k) == 0);
                    unsigned long long a = keys[i], b = keys[ixj];
                    if (desc ? (a < b) : (a > b)) { keys[i] = b; keys[ixj] = a; }
                }
            }
            __syncthreads();
        }
    }
    for (int r = t; r < n; r += 1024) {
        int o = (int)(0xFFFFFFFFu - (unsigned)keys[r]);
        g_sord[r] = o;
        float4 b = ((const float4*)boxes)[o];
        ((float4*)g_sbx)[r] = b;
        g_sar[r] = fmaxf(b.z - b.x, 0.f) * fmaxf(b.w - b.y, 0.f);
    }
}

// ---------------- S2: parallel suppression-bitmask build ----------------
__global__ void __launch_bounds__(1024) k_mask(int stage) {
    extern __shared__ float s[];
    const int n = stage ? N_PROP : NA;
    const int W = (n + 63) >> 6;
    const float thr = stage ? 0.3f : 0.5f;
    float4* sb = (float4*)s;
    float* sa = s + n * 4;
    int t = threadIdx.x, c = blockIdx.x;
    for (int j = t; j < n; j += 1024) {
        sb[j] = ((const float4*)g_sbx)[j];
        sa[j] = g_sar[j];
    }
    __syncthreads();
    int il = t >> 4;
    int i = c * 64 + il;
    if (i >= n) return;
    float4 bi = sb[i];
    float ai = sa[i];
    for (int w = (t & 15); w < W; w += 16) {
        unsigned long long m = 0ull;
        int jb = w << 6;
#pragma unroll 8
        for (int bb = 0; bb < 64; bb++) {
            int j = jb + bb;
            if (j < n && j > i) {
                float4 bj = sb[j];
                float inter = fmaxf(fminf(bi.z, bj.z) - fmaxf(bi.x, bj.x), 0.f) *
                              fmaxf(fminf(bi.w, bj.w) - fmaxf(bi.y, bj.y), 0.f);
                if (inter / (ai + sa[j] - inter + 1e-8f) > thr) m |= 1ull << bb;
            }
        }
        g_mask[(size_t)i * W + w] = m;
    }
}

// ---------------- S3: greedy scan over precomputed masks + epilogue ----------------
__global__ void __launch_bounds__(1024, 1) k_scan(int stage, float* __restrict__ out) {
    __shared__ unsigned long long diag[64];
    __shared__ unsigned long long keepw[64];
    __shared__ unsigned long long lkbc;
    __shared__ int scan[1024];
    const int n = stage ? N_PROP : NA;
    const int W = (n + 63) >> 6;
    int t = threadIdx.x;  // 1024

    if (t < W) {
        int nb = n - t * 64;
        keepw[t] = (nb >= 64) ? ~0ull : ((1ull << nb) - 1ull);
    }
    __syncthreads();

    for (int c = 0; c < W; c++) {
        if (t < 64) {
            int i = c * 64 + t;
            diag[t] = (i < n) ? g_mask[(size_t)i * W + c] : 0ull;
        }
        __syncthreads();
        if (t == 0) {
            unsigned long long lk = keepw[c];
#pragma unroll 8
            for (int i = 0; i < 64; i++)
                if ((lk >> i) & 1ull) lk &= ~diag[i];
            keepw[c] = lk;
            lkbc = lk;
        }
        __syncthreads();
        unsigned long long lk = lkbc;
        if (lk) {
            for (int p = t; p < 64 * W; p += 1024) {
                int i = p / W, w = p - i * W;
                if (w > c && ((lk >> i) & 1ull)) {
                    unsigned long long m = g_mask[(size_t)(c * 64 + i) * W + w];
                    if (m) atomicAnd(&keepw[w], ~m);
                }
            }
        }
        __syncthreads();
    }

    if (stage == 0) {
        int b0 = t * 3;
        unsigned char ks[3] = {0, 0, 0};
        int csum = 0;
#pragma unroll
        for (int q = 0; q < 3; q++) {
            int i = b0 + q;
            if (i < n) {
                ks[q] = (unsigned char)((keepw[i >> 6] >> (i & 63)) & 1ull);
                csum += ks[q];
            }
        }
        scan[t] = csum;
        __syncthreads();
        for (int off = 1; off < 1024; off <<= 1) {
            int v = (t >= off) ? scan[t - off] : 0;
            __syncthreads();
            scan[t] += v;
            __syncthreads();
        }
        int K = scan[1023];
        int rk = scan[t] - csum;
#pragma unroll
        for (int q = 0; q < 3; q++) {
            int i = b0 + q;
            if (i >= n) break;
            int slot;
            if (ks[q]) { slot = rk; rk++; }
            else       { slot = K + (i - rk); }
            if (slot < N_PROP) {
                g_valid[slot] = ks[q];
                float4 v = make_float4(0.f, 0.f, 0.f, 0.f);
                if (ks[q]) v = ((const float4*)g_sbx)[i];
                ((float4*)g_prop)[slot] = v;
                out[OFF_PROPOSALS + slot * 4 + 0] = v.x;
                out[OFF_PROPOSALS + slot * 4 + 1] = v.y;
                out[OFF_PROPOSALS + slot * 4 + 2] = v.z;
                out[OFF_PROPOSALS + slot * 4 + 3] = v.w;
            }
        }
    } else {
        for (int r = t; r < n; r += 1024) {
            g_order2[r] = g_sord[r];
            g_keep2[r] = (unsigned char)((keepw[r >> 6] >> (r & 63)) & 1ull);
            ((float4*)g_sdets)[r] = ((const float4*)g_sbx)[r];
        }
    }
}

// ---------------- weight prepack: wm1 -> packed co-pair u64 ----------------
__global__ void k_wpack(const float* __restrict__ wm1) {
    int i = blockIdx.x * 256 + threadIdx.x;  // < 32*576
    int cp = i / 576, k = i - cp * 576;
    g_wpack[cp * 576 + k] = pk2(wm1[(2 * cp) * 576 + k], wm1[(2 * cp + 1) * 576 + k]);
}

// ---------------- fused ROI: dup-crops, 512 threads (4 row-groups) ----------------
#define CSTR 576  // per-ci dup floats: 16 rows x 36 (row stride 144B, bank-disjoint quarters)
#define CROW 36
#define ROI_SMEM_BYTES (64 * CSTR * 4 + 512)

// outputs rows I0..I0+NI-1; reads input rows I0..I0+NI+1 (padded layout)
template <int I0, int NI>
__device__ __forceinline__ void conv_rows(const float* base,
                                          const unsigned long long* w2,
                                          unsigned long long* acc) {
#pragma unroll
    for (int r = I0; r < I0 + NI + 2; r++) {
        unsigned long long d[9];
#pragma unroll
        for (int c2 = 0; c2 < 9; c2++)
            d[c2] = *(const unsigned long long*)&base[r * CROW + 2 * c2];
#pragma unroll
        for (int dy = 0; dy < 3; dy++) {
            int i = r - dy;
            if (i >= I0 && i < I0 + NI) {
#pragma unroll
                for (int j = 0; j < 7; j++) {
                    fma2(acc[(i - I0) * 7 + j], d[j + 0], w2[dy * 3 + 0]);
                    fma2(acc[(i - I0) * 7 + j], d[j + 1], w2[dy * 3 + 1]);
                    fma2(acc[(i - I0) * 7 + j], d[j + 2], w2[dy * 3 + 2]);
                }
            }
        }
    }
}

__global__ void __launch_bounds__(512, 1)
k_roi(const float* __restrict__ bm1, const float* __restrict__ wm2,
      const float* __restrict__ bm2, float* __restrict__ out) {
    extern __shared__ float smf[];
    float* cd = smf;                    // 64 x CSTR, values duplicated: (v,v) at 2*col
    float* aux = smf + 64 * CSTR;       // 512 B
    float* wy = aux;
    float* wx = aux + 14;
    int* y0 = (int*)(aux + 28);
    int* y1 = y0 + 14;
    int* x0 = y1 + 14;
    int* x1 = x0 + 14;

    int n = blockIdx.x, t = threadIdx.x;  // 512

    unsigned long long* cz = (unsigned long long*)cd;
    for (int i = t; i < 64 * CSTR / 2; i += 512) cz[i] = 0ull;
    if (t < 28) {
        int i = t % 14;
        bool isY = t < 14;
        float c1 = g_prop[n * 4 + (isY ? 1 : 0)] * (1.f / 255.f);
        float c2 = g_prop[n * 4 + (isY ? 3 : 2)] * (1.f / 255.f);
        float f = (c1 + (c2 - c1) * ((float)i / 13.f)) * 15.f;
        float f0 = fminf(fmaxf(floorf(f), 0.f), 15.f);
        int i0 = (int)f0, i1 = min(i0 + 1, 15);
        float wgt = f - f0;
        if (isY) { y0[i] = i0; y1[i] = i1; wy[i] = wgt; }
        else     { x0[i] = i0; x1[i] = i1; wx[i] = wgt; }
    }
    __syncthreads();

    // bilinear crop, written duplicated
    for (int idx = t; idx < 64 * 196; idx += 512) {
        int c = idx / 196, p = idx % 196, i = p / 14, j = p % 14;
        const float* f = g_feat + c * 256;
        float v00 = f[y0[i] * 16 + x0[j]], v01 = f[y0[i] * 16 + x1[j]];
        float v10 = f[y1[i] * 16 + x0[j]], v11 = f[y1[i] * 16 + x1[j]];
        float top = v00 * (1.f - wx[j]) + v01 * wx[j];
        float bot = v10 * (1.f - wx[j]) + v11 * wx[j];
        float v = top * (1.f - wy[i]) + bot * wy[i];
        *(unsigned long long*)&cd[c * CSTR + (i + 1) * CROW + 2 * (j + 1)] = pk2(v, v);
    }
    __syncthreads();

    // 2x2 maxpool -> g_pooled (read lo copies)
    for (int idx = t; idx < FC1_K; idx += 512) {
        int c = idx / 49, p = idx % 49, pi = p / 7, pj = p % 7;
        const float* b = cd + c * CSTR + (2 * pi + 1) * CROW + (2 * pj + 1) * 2;
        g_pooled[n * FC1_K + idx] =
            fmaxf(fmaxf(b[0], b[2]), fmaxf(b[CROW], b[CROW + 2]));
    }

    // mask conv1: thread = (h2 = t>>7 [warp-uniform row group], cp = (t>>2)&31, q = t&3)
    int h2 = t >> 7, cp = (t >> 2) & 31, q = t & 3;
    int qy = q >> 1, qx = q & 1;
    unsigned long long acc[14];
#pragma unroll
    for (int p = 0; p < 14; p++) acc[p] = 0ull;
    const unsigned long long* wrow = g_wpack + cp * 576;

    // double-buffered weight prefetch
    unsigned long long wbuf[2][9];
#pragma unroll
    for (int k = 0; k < 9; k++) wbuf[0][k] = __ldg(&wrow[k]);
#pragma unroll 2
    for (int ci = 0; ci < 64; ci++) {
        const int cur = ci & 1;
        if (ci + 1 < 64) {
#pragma unroll
            for (int k = 0; k < 9; k++) wbuf[cur ^ 1][k] = __ldg(&wrow[(ci + 1) * 9 + k]);
        }
        const unsigned long long* w2 = wbuf[cur];
        const float* base = cd + ci * CSTR + qy * 7 * CROW + qx * 14;
        if (h2 == 0)      conv_rows<0, 2>(base, w2, acc);
        else if (h2 == 1) conv_rows<2, 2>(base, w2, acc);
        else if (h2 == 2) conv_rows<4, 2>(base, w2, acc);
        else              conv_rows<6, 1>(base, w2, acc);
    }
    int co0 = 2 * cp;
    float b10 = bm1[co0], b11 = bm1[co0 + 1];
    float w20 = wm2[co0], w21 = wm2[co0 + 1];
    __syncthreads();  // conv + maxpool reads of cd done

    // relu + 1x1 partials into reused smem: part[co*196 + q*49 + pp]
    float* part = cd;
    int I0v = h2 * 2, cnt = (h2 == 3) ? 7 : 14;
#pragma unroll
    for (int p = 0; p < 14; p++) {
        if (p < cnt) {
            float lo, hi;
            upk2(acc[p], lo, hi);
            int pp = q * 49 + (I0v + p / 7) * 7 + (p % 7);
            part[co0 * 196 + pp] = fmaxf(lo + b10, 0.f) * w20;
            part[(co0 + 1) * 196 + pp] = fmaxf(hi + b11, 0.f) * w21;
        }
    }
    __syncthreads();

    if (t < 196) {
        float s = bm2[0];
#pragma unroll 8
        for (int c = 0; c < 64; c++) s += part[c * 196 + t];
        int qq = t / 49, p2 = t % 49;
        int gi = (qq >> 1) * 7 + p2 / 7, gj = (qq & 1) * 7 + p2 % 7;
        out[OFF_RCNN_MASKS + n * 196 + gi * 14 + gj] = s;
    }
}

// ---------------- tiled GEMM (f32x2, R7 version) ----------------
__global__ void k_gemm(int which, const float* __restrict__ B,
                       const float* __restrict__ bias) {
    const float* A = which ? g_h1 : g_pooled;
    float* C = which ? g_h2 : g_h1;
    const int K = which ? 512 : FC1_K;
    const int M = N_PROP, N = 512;

    __shared__ float As[16][68];
    __shared__ float Bs[16][64];
    int tid = threadIdx.x;
    int m0 = blockIdx.x * 64, n0 = blockIdx.y * 64;
    int ty = tid >> 4, tx = tid & 15;
    unsigned long long acc2[4][2];
#pragma unroll
    for (int i = 0; i < 4; i++) { acc2[i][0] = 0ull; acc2[i][1] = 0ull; }

    int ra = tid >> 2, ca = (tid & 3) * 4;
    int rb = tid >> 4, cb = (tid & 15) * 4;

    for (int k0 = 0; k0 < K; k0 += 16) {
        float4 a4 = make_float4(0.f, 0.f, 0.f, 0.f);
        int m = m0 + ra;
        if (m < M) a4 = *(const float4*)&A[(size_t)m * K + k0 + ca];
        As[ca + 0][ra] = a4.x; As[ca + 1][ra] = a4.y;
        As[ca + 2][ra] = a4.z; As[ca + 3][ra] = a4.w;
        float4 b4 = *(const float4*)&B[(size_t)(k0 + rb) * N + n0 + cb];
        *(float4*)&Bs[rb][cb] = b4;
        __syncthreads();
#pragma unroll
        for (int kk = 0; kk < 16; kk++) {
            float4 av = *(const float4*)&As[kk][ty * 4];
            unsigned long long a0 = dup2(av.x), a1 = dup2(av.y);
            unsigned long long a2 = dup2(av.z), a3 = dup2(av.w);
            unsigned long long b0 = *(const unsigned long long*)&Bs[kk][tx * 4];
            unsigned long long b1 = *(const unsigned long long*)&Bs[kk][tx * 4 + 2];
            fma2(acc2[0][0], a0, b0); fma2(acc2[0][1], a0, b1);
            fma2(acc2[1][0], a1, b0); fma2(acc2[1][1], a1, b1);
            fma2(acc2[2][0], a2, b0); fma2(acc2[2][1], a2, b1);
            fma2(acc2[3][0], a3, b0); fma2(acc2[3][1], a3, b1);
        }
        __syncthreads();
    }
#pragma unroll
    for (int i = 0; i < 4; i++) {
        int m = m0 + ty * 4 + i;
        if (m < M) {
#pragma unroll
            for (int jp = 0; jp < 2; jp++) {
                float lo, hi;
                upk2(acc2[i][jp], lo, hi);
                int nc = n0 + tx * 4 + jp * 2;
                C[(size_t)m * N + nc]     = fmaxf(lo + bias[nc], 0.f);
                C[(size_t)m * N + nc + 1] = fmaxf(hi + bias[nc + 1], 0.f);
            }
        }
    }
}

// ---------------- RCNN heads + decode ----------------
__device__ __forceinline__ float wred(float v) {
#pragma unroll
    for (int o = 16; o; o >>= 1) v += __shfl_xor_sync(0xFFFFFFFFu, v, o);
    return v;
}

__global__ void k_rhead(const float* __restrict__ wrcls, const float* __restrict__ brcls,
                        const float* __restrict__ wrbox, const float* __restrict__ brbox,
                        float* __restrict__ out) {
    int w = threadIdx.x >> 5, lane = threadIdx.x & 31;
    int n = blockIdx.x * 8 + w;
    const float* h = g_h2 + n * 512;
    float p[6];
#pragma unroll
    for (int o = 0; o < 6; o++) p[o] = 0.f;
    for (int k = lane; k < 512; k += 32) {
        float hv = h[k];
        p[0] += hv * wrcls[k * 2 + 0];
        p[1] += hv * wrcls[k * 2 + 1];
        p[2] += hv * wrbox[k * 4 + 0];
        p[3] += hv * wrbox[k * 4 + 1];
        p[4] += hv * wrbox[k * 4 + 2];
        p[5] += hv * wrbox[k * 4 + 3];
    }
#pragma unroll
    for (int o = 0; o < 6; o++) p[o] = wred(p[o]);
    if (lane == 0) {
        float l0 = p[0] + brcls[0], l1 = p[1] + brcls[1];
        float d0 = p[2] + brbox[0], d1 = p[3] + brbox[1];
        float d2 = p[4] + brbox[2], d3 = p[5] + brbox[3];
        out[OFF_RCNN_LOGITS + n * 2 + 0] = l0;
        out[OFF_RCNN_LOGITS + n * 2 + 1] = l1;
        out[OFF_RCNN_DELTAS + n * 4 + 0] = d0;
        out[OFF_RCNN_DELTAS + n * 4 + 1] = d1;
        out[OFF_RCNN_DELTAS + n * 4 + 2] = d2;
        out[OFF_RCNN_DELTAS + n * 4 + 3] = d3;
        float mx = fmaxf(l0, l1);
        float e0 = expf(l0 - mx), e1 = expf(l1 - mx);
        float ds = e1 / (e0 + e1);
        g_dscores[n] = ds;
        float px1 = g_prop[n * 4], py1 = g_prop[n * 4 + 1];
        float px2 = g_prop[n * 4 + 2], py2 = g_prop[n * 4 + 3];
        float pw = px2 - px1, ph = py2 - py1;
        float cx = px1 + 0.5f * pw, cy = py1 + 0.5f * ph;
        float ncx = cx + d0 * pw, ncy = cy + d1 * ph;
        float nw = pw * expf(d2), nh = ph * expf(d3);
        g_dets[n * 4 + 0] = fminf(fmaxf(ncx - 0.5f * nw, 0.f), 255.f);
        g_dets[n * 4 + 1] = fminf(fmaxf(ncy - 0.5f * nh, 0.f), 255.f);
        g_dets[n * 4 + 2] = fminf(fmaxf(ncx + 0.5f * nw, 0.f), 255.f);
        g_dets[n * 4 + 3] = fminf(fmaxf(ncy + 0.5f * nh, 0.f), 255.f);
        g_s2[n] = g_valid[n] ? ds : -1.0f;
    }
}

// ---------------- finalize ----------------
__global__ void k_finalize(float* __restrict__ out) {
    int r = blockIdx.x, t = threadIdx.x;
    int o2 = g_order2[r];
    bool comb = g_keep2[r] && g_valid[o2];
    if (t == 0) {
        out[OFF_KEEP2 + r] = comb ? 1.f : 0.f;
        out[OFF_FINAL_SCORES + r] = comb ? g_dscores[o2] : 0.f;
        out[OFF_FINAL_DETS + r * 4 + 0] = comb ? g_sdets[r * 4 + 0] : 0.f;
        out[OFF_FINAL_DETS + r * 4 + 1] = comb ? g_sdets[r * 4 + 1] : 0.f;
        out[OFF_FINAL_DETS + r * 4 + 2] = comb ? g_sdets[r * 4 + 2] : 0.f;
        out[OFF_FINAL_DETS + r * 4 + 3] = comb ? g_sdets[r * 4 + 3] : 0.f;
    }
    if (t < 196) {
        float m = out[OFF_RCNN_MASKS + o2 * 196 + t];
        out[OFF_FINAL_MASKS + r * 196 + t] = comb ? (1.f / (1.f + expf(-m))) : 0.f;
    }
}

// ---------------- launch ----------------
extern "C" void kernel_launch(void* const* d_in, const int* in_sizes, int n_in,
                              void* d_out, int out_size) {
    const float* x      = (const float*)d_in[0];
    const float* w_bb   = (const float*)d_in[1];
    const float* b_bb   = (const float*)d_in[2];
    const float* w_rpn  = (const float*)d_in[3];
    const float* b_rpn  = (const float*)d_in[4];
    const float* w_cls  = (const float*)d_in[5];
    const float* b_cls  = (const float*)d_in[6];
    const float* w_box  = (const float*)d_in[7];
    const float* b_box  = (const float*)d_in[8];
    const float* w_fc1  = (const float*)d_in[9];
    const float* b_fc1  = (const float*)d_in[10];
    const float* w_fc2  = (const float*)d_in[11];
    const float* b_fc2  = (const float*)d_in[12];
    const float* w_rcls = (const float*)d_in[13];
    const float* b_rcls = (const float*)d_in[14];
    const float* w_rbox = (const float*)d_in[15];
    const float* b_rbox = (const float*)d_in[16];
    const float* w_m1   = (const float*)d_in[17];
    const float* b_m1   = (const float*)d_in[18];
    const float* w_m2   = (const float*)d_in[19];
    const float* b_m2   = (const float*)d_in[20];
    float* out = (float*)d_out;

    cudaFuncSetAttribute(k_roi, cudaFuncAttributeMaxDynamicSharedMemorySize, ROI_SMEM_BYTES);

    k_backbone<<<256, 64>>>(x, w_bb, b_bb);
    k_rpnconv<<<64, 256>>>(w_rpn, b_rpn);
    k_rpnhead<<<256, 64>>>(w_cls, b_cls, w_box, b_box, out);

    k_sort<4096><<<1, 1024>>>(0);
    k_mask<<<36, 1024, NA * 20>>>(0);
    k_scan<<<1, 1024>>>(0, out);

    k_wpack<<<72, 256>>>(w_m1);
    k_roi<<<N_PROP, 512, ROI_SMEM_BYTES>>>(b_m1, w_m2, b_m2, out);
    {
        dim3 g1(32, 8);
        k_gemm<<<g1, 256>>>(0, w_fc1, b_fc1);
        k_gemm<<<g1, 256>>>(1, w_fc2, b_fc2);
    }
    k_rhead<<<250, 256>>>(w_rcls, b_rcls, w_rbox, b_rbox, out);

    k_sort<2048><<<1, 1024>>>(1);
    k_mask<<<32, 1024, N_PROP * 20>>>(1);
    k_scan<<<1, 1024>>>(1, out);

    k_finalize<<<N_PROP, 256>>>(out);
}

// round 12
// speedup vs baseline: 1.2685x; 1.2685x over previous
#include <cuda_runtime.h>
#include <math.h>

#define NA 2304
#define N_PROP 2000
#define FC1_K 3136
#define WMAX 36

#define OFF_RPN_LOGITS   0
#define OFF_RPN_DELTAS   4608
#define OFF_PROPOSALS    13824
#define OFF_ANCHORS      21824
#define OFF_RCNN_LOGITS  31040
#define OFF_RCNN_DELTAS  35040
#define OFF_RCNN_MASKS   43040
#define OFF_FINAL_DETS   435040
#define OFF_FINAL_MASKS  443040
#define OFF_FINAL_SCORES 835040
#define OFF_KEEP2        837040

// ---------------- scratch ----------------
__device__ __align__(16) float g_feat[64 * 256];
__device__ __align__(16) float g_h[64 * 256];
__device__ __align__(16) float g_scores[NA];
__device__ __align__(16) float g_boxes[NA * 4];
__device__ __align__(16) float g_sbx[NA * 4];
__device__ float g_sar[NA];
__device__ int   g_sord[NA];
__device__ unsigned long long g_mask[NA * WMAX];
__device__ __align__(16) float g_prop[N_PROP * 4];
__device__ unsigned char g_valid[N_PROP];
__device__ __align__(16) float g_pooled[N_PROP * FC1_K];
__device__ __align__(16) float g_h1[N_PROP * 512];
__device__ __align__(16) float g_h2[N_PROP * 512];
__device__ __align__(16) float g_dets[N_PROP * 4];
__device__ __align__(16) float g_sdets[N_PROP * 4];
__device__ float g_dscores[N_PROP];
__device__ float g_s2[N_PROP];
__device__ int   g_order2[N_PROP];
__device__ unsigned char g_keep2[N_PROP];
__device__ __align__(16) unsigned long long g_wpack[32 * 576];  // packed co-pair mask weights

// ---------------- f32x2 helpers ----------------
__device__ __forceinline__ void fma2(unsigned long long& d, unsigned long long a,
                                     unsigned long long b) {
    asm("fma.rn.f32x2 %0, %1, %2, %0;" : "+l"(d) : "l"(a), "l"(b));
}
__device__ __forceinline__ unsigned long long dup2(float x) {
    unsigned long long r;
    asm("mov.b64 %0, {%1, %1};" : "=l"(r) : "f"(x));
    return r;
}
__device__ __forceinline__ unsigned long long pk2(float lo, float hi) {
    unsigned long long r;
    asm("mov.b64 %0, {%1, %2};" : "=l"(r) : "f"(lo), "f"(hi));
    return r;
}
__device__ __forceinline__ void upk2(unsigned long long v, float& lo, float& hi) {
    asm("mov.b64 {%0, %1}, %2;" : "=f"(lo), "=f"(hi) : "l"(v));
}

// ---------------- backbone ----------------
__global__ void k_backbone(const float* __restrict__ x, const float* __restrict__ w,
                           const float* __restrict__ b) {
    __shared__ float patch[768];
    int pos = blockIdx.x, py = pos >> 4, px = pos & 15;
    int t = threadIdx.x;  // 64
    for (int i = t; i < 768; i += 64) {
        int ci = i >> 8, rem = i & 255, ky = rem >> 4, kx = rem & 15;
        patch[i] = x[ci * 65536 + (py * 16 + ky) * 256 + (px * 16 + kx)];
    }
    __syncthreads();
    const float* wc = w + t * 768;
    float acc = b[t];
#pragma unroll 8
    for (int i = 0; i < 768; i++) acc += patch[i] * __ldg(&wc[i]);
    g_feat[t * 256 + pos] = fmaxf(acc, 0.f);
}

// ---------------- RPN 3x3 SAME conv ----------------
__global__ void k_rpnconv(const float* __restrict__ w, const float* __restrict__ b) {
    __shared__ float ws[576];
    int c = blockIdx.x, t = threadIdx.x;  // 256
    for (int i = t; i < 576; i += 256) ws[i] = w[c * 576 + i];
    __syncthreads();
    int y = t >> 4, x = t & 15;
    float acc = b[c];
    for (int ci = 0; ci < 64; ci++) {
        const float* f = g_feat + ci * 256;
#pragma unroll
        for (int ky = 0; ky < 3; ky++) {
            int yy = y + ky - 1;
            if (yy < 0 || yy > 15) continue;
#pragma unroll
            for (int kx = 0; kx < 3; kx++) {
                int xx = x + kx - 1;
                if (xx < 0 || xx > 15) continue;
                acc += __ldg(&f[yy * 16 + xx]) * ws[ci * 9 + ky * 3 + kx];
            }
        }
    }
    g_h[c * 256 + t] = fmaxf(acc, 0.f);
}

// ---------------- RPN heads + anchors + decode + clip ----------------
__global__ void k_rpnhead(const float* __restrict__ wcls, const float* __restrict__ bcls,
                          const float* __restrict__ wbox, const float* __restrict__ bbox,
                          float* __restrict__ out) {
    __shared__ float hv[64], lg[18], dl[36];
    int pos = blockIdx.x, y = pos >> 4, x = pos & 15;
    int t = threadIdx.x;  // 64
    hv[t] = g_h[t * 256 + pos];
    __syncthreads();
    if (t < 54) {
        int a = t / 6, j = t % 6;
        if (j < 2) {
            int o = a * 2 + j;
            float acc = bcls[o];
            const float* wr = wcls + o * 64;
            for (int ci = 0; ci < 64; ci++) acc += hv[ci] * wr[ci];
            lg[o] = acc;
            out[OFF_RPN_LOGITS + (pos * 9 + a) * 2 + j] = acc;
        } else {
            int o = a * 4 + (j - 2);
            float acc = bbox[o];
            const float* wr = wbox + o * 64;
            for (int ci = 0; ci < 64; ci++) acc += hv[ci] * wr[ci];
            dl[o] = acc;
            out[OFF_RPN_DELTAS + (pos * 9 + a) * 4 + (j - 2)] = acc;
        }
    }
    __syncthreads();
    if (t < 9) {
        int a = t;
        float l0 = lg[a * 2], l1 = lg[a * 2 + 1];
        float mx = fmaxf(l0, l1);
        float e0 = expf(l0 - mx), e1 = expf(l1 - mx);
        float sc = e1 / (e0 + e1);
        const float scl[3] = {32.f, 64.f, 128.f};
        const float rat[3] = {0.5f, 1.f, 2.f};
        float s = scl[a / 3], r = rat[a % 3];
        float ws = s * sqrtf(r), hs = s / sqrtf(r);
        float cx = ((float)x + 0.5f) * 16.f, cy = ((float)y + 0.5f) * 16.f;
        float a0 = cx - ws * 0.5f, a1 = cy - hs * 0.5f;
        float a2 = cx + ws * 0.5f, a3 = cy + hs * 0.5f;
        int ai = pos * 9 + a;
        out[OFF_ANCHORS + ai * 4 + 0] = a0;
        out[OFF_ANCHORS + ai * 4 + 1] = a1;
        out[OFF_ANCHORS + ai * 4 + 2] = a2;
        out[OFF_ANCHORS + ai * 4 + 3] = a3;
        float w = a2 - a0, h = a3 - a1;
        float ccx = a0 + 0.5f * w, ccy = a1 + 0.5f * h;
        float ncx = ccx + dl[a * 4 + 0] * w, ncy = ccy + dl[a * 4 + 1] * h;
        float nw = w * expf(dl[a * 4 + 2]), nh = h * expf(dl[a * 4 + 3]);
        g_scores[ai] = sc;
        g_boxes[ai * 4 + 0] = fminf(fmaxf(ncx - 0.5f * nw, 0.f), 255.f);
        g_boxes[ai * 4 + 1] = fminf(fmaxf(ncy - 0.5f * nh, 0.f), 255.f);
        g_boxes[ai * 4 + 2] = fminf(fmaxf(ncx + 0.5f * nw, 0.f), 255.f);
        g_boxes[ai * 4 + 3] = fminf(fmaxf(ncy + 0.5f * nh, 0.f), 255.f);
    }
}

// ---------------- S1: stable descending sort ----------------
__device__ __forceinline__ unsigned int fmap(float s) {
    unsigned int u = __float_as_uint(s);
    return (u & 0x80000000u) ? ~u : (u | 0x80000000u);
}

template <int P>
__global__ void __launch_bounds__(1024, 1) k_sort(int stage) {
    __shared__ unsigned long long keys[P];
    const int n = stage ? N_PROP : NA;
    const float* scores = stage ? g_s2 : g_scores;
    const float* boxes = stage ? g_dets : g_boxes;
    int t = threadIdx.x;  // 1024
#pragma unroll
    for (int s = 0; s < P / 1024; s++) {
        int i = t + s * 1024;
        unsigned long long k = 0ull;
        if (i < n)
            k = ((unsigned long long)fmap(scores[i]) << 32) |
                (unsigned long long)(0xFFFFFFFFu - (unsigned)i);
        keys[i] = k;
    }
    __syncthreads();
    for (int k = 2; k <= P; k <<= 1) {
        for (int j = k >> 1; j > 0; j >>= 1) {
#pragma unroll
            for (int s = 0; s < P / 1024; s++) {
                int i = t + s * 1024;
                int ixj = i ^ j;
                if (ixj > i) {
                    bool desc = ((i & k) == 0);
                    unsigned long long a = keys[i], b = keys[ixj];
                    if (desc ? (a < b) : (a > b)) { keys[i] = b; keys[ixj] = a; }
                }
            }
            __syncthreads();
        }
    }
    for (int r = t; r < n; r += 1024) {
        int o = (int)(0xFFFFFFFFu - (unsigned)keys[r]);
        g_sord[r] = o;
        float4 b = ((const float4*)boxes)[o];
        ((float4*)g_sbx)[r] = b;
        g_sar[r] = fmaxf(b.z - b.x, 0.f) * fmaxf(b.w - b.y, 0.f);
    }
}

// ---------------- S2: parallel suppression-bitmask build ----------------
__global__ void __launch_bounds__(1024) k_mask(int stage) {
    extern __shared__ float s[];
    const int n = stage ? N_PROP : NA;
    const int W = (n + 63) >> 6;
    const float thr = stage ? 0.3f : 0.5f;
    float4* sb = (float4*)s;
    float* sa = s + n * 4;
    int t = threadIdx.x, c = blockIdx.x;
    for (int j = t; j < n; j += 1024) {
        sb[j] = ((const float4*)g_sbx)[j];
        sa[j] = g_sar[j];
    }
    __syncthreads();
    int il = t >> 4;
    int i = c * 64 + il;
    if (i >= n) return;
    float4 bi = sb[i];
    float ai = sa[i];
    for (int w = (t & 15); w < W; w += 16) {
        unsigned long long m = 0ull;
        int jb = w << 6;
#pragma unroll 8
        for (int bb = 0; bb < 64; bb++) {
            int j = jb + bb;
            if (j < n && j > i) {
                float4 bj = sb[j];
                float inter = fmaxf(fminf(bi.z, bj.z) - fmaxf(bi.x, bj.x), 0.f) *
                              fmaxf(fminf(bi.w, bj.w) - fmaxf(bi.y, bj.y), 0.f);
                if (inter / (ai + sa[j] - inter + 1e-8f) > thr) m |= 1ull << bb;
            }
        }
        g_mask[(size_t)i * W + w] = m;
    }
}

// ---------------- S3: greedy scan over precomputed masks + epilogue ----------------
__global__ void __launch_bounds__(1024, 1) k_scan(int stage, float* __restrict__ out) {
    __shared__ unsigned long long diag[64];
    __shared__ unsigned long long keepw[64];
    __shared__ unsigned long long lkbc;
    __shared__ int scan[1024];
    const int n = stage ? N_PROP : NA;
    const int W = (n + 63) >> 6;
    int t = threadIdx.x;  // 1024

    if (t < W) {
        int nb = n - t * 64;
        keepw[t] = (nb >= 64) ? ~0ull : ((1ull << nb) - 1ull);
    }
    __syncthreads();

    for (int c = 0; c < W; c++) {
        if (t < 64) {
            int i = c * 64 + t;
            diag[t] = (i < n) ? g_mask[(size_t)i * W + c] : 0ull;
        }
        __syncthreads();
        if (t == 0) {
            unsigned long long lk = keepw[c];
#pragma unroll 8
            for (int i = 0; i < 64; i++)
                if ((lk >> i) & 1ull) lk &= ~diag[i];
            keepw[c] = lk;
            lkbc = lk;
        }
        __syncthreads();
        unsigned long long lk = lkbc;
        if (lk) {
            for (int p = t; p < 64 * W; p += 1024) {
                int i = p / W, w = p - i * W;
                if (w > c && ((lk >> i) & 1ull)) {
                    unsigned long long m = g_mask[(size_t)(c * 64 + i) * W + w];
                    if (m) atomicAnd(&keepw[w], ~m);
                }
            }
        }
        __syncthreads();
    }

    if (stage == 0) {
        int b0 = t * 3;
        unsigned char ks[3] = {0, 0, 0};
        int csum = 0;
#pragma unroll
        for (int q = 0; q < 3; q++) {
            int i = b0 + q;
            if (i < n) {
                ks[q] = (unsigned char)((keepw[i >> 6] >> (i & 63)) & 1ull);
                csum += ks[q];
            }
        }
        scan[t] = csum;
        __syncthreads();
        for (int off = 1; off < 1024; off <<= 1) {
            int v = (t >= off) ? scan[t - off] : 0;
            __syncthreads();
            scan[t] += v;
            __syncthreads();
        }
        int K = scan[1023];
        int rk = scan[t] - csum;
#pragma unroll
        for (int q = 0; q < 3; q++) {
            int i = b0 + q;
            if (i >= n) break;
            int slot;
            if (ks[q]) { slot = rk; rk++; }
            else       { slot = K + (i - rk); }
            if (slot < N_PROP) {
                g_valid[slot] = ks[q];
                float4 v = make_float4(0.f, 0.f, 0.f, 0.f);
                if (ks[q]) v = ((const float4*)g_sbx)[i];
                ((float4*)g_prop)[slot] = v;
                out[OFF_PROPOSALS + slot * 4 + 0] = v.x;
                out[OFF_PROPOSALS + slot * 4 + 1] = v.y;
                out[OFF_PROPOSALS + slot * 4 + 2] = v.z;
                out[OFF_PROPOSALS + slot * 4 + 3] = v.w;
            }
        }
    } else {
        for (int r = t; r < n; r += 1024) {
            g_order2[r] = g_sord[r];
            g_keep2[r] = (unsigned char)((keepw[r >> 6] >> (r & 63)) & 1ull);
            ((float4*)g_sdets)[r] = ((const float4*)g_sbx)[r];
        }
    }
}

// ---------------- weight prepack: wm1 -> packed co-pair u64 ----------------
__global__ void k_wpack(const float* __restrict__ wm1) {
    int i = blockIdx.x * 256 + threadIdx.x;  // < 32*576
    int cp = i / 576, k = i - cp * 576;
    g_wpack[cp * 576 + k] = pk2(wm1[(2 * cp) * 576 + k], wm1[(2 * cp + 1) * 576 + k]);
}

// ---------------- fused ROI: plain crops (66KB smem -> 2 CTAs/SM) ----------------
#define ROI_SMEM_BYTES (16384 * 4 + 512)

__global__ void __launch_bounds__(256, 2)
k_roi(const float* __restrict__ bm1, const float* __restrict__ wm2,
      const float* __restrict__ bm2, float* __restrict__ out) {
    extern __shared__ float smf[];
    float* crops = smf;              // 64 x 16 x 16 padded (data at [i+1][j+1])
    float* aux = smf + 16384;        // 512 B
    float* wy = aux;
    float* wx = aux + 14;
    int* y0 = (int*)(aux + 28);
    int* y1 = y0 + 14;
    int* x0 = y1 + 14;
    int* x1 = x0 + 14;

    int n = blockIdx.x, t = threadIdx.x;  // 256

    for (int i = t; i < 16384; i += 256) crops[i] = 0.f;
    if (t < 28) {
        int i = t % 14;
        bool isY = t < 14;
        float c1 = g_prop[n * 4 + (isY ? 1 : 0)] * (1.f / 255.f);
        float c2 = g_prop[n * 4 + (isY ? 3 : 2)] * (1.f / 255.f);
        float f = (c1 + (c2 - c1) * ((float)i / 13.f)) * 15.f;
        float f0 = fminf(fmaxf(floorf(f), 0.f), 15.f);
        int i0 = (int)f0, i1 = min(i0 + 1, 15);
        float wgt = f - f0;
        if (isY) { y0[i] = i0; y1[i] = i1; wy[i] = wgt; }
        else     { x0[i] = i0; x1[i] = i1; wx[i] = wgt; }
    }
    __syncthreads();

    // bilinear crop
    for (int idx = t; idx < 64 * 196; idx += 256) {
        int c = idx / 196, p = idx % 196, i = p / 14, j = p % 14;
        const float* f = g_feat + c * 256;
        float v00 = f[y0[i] * 16 + x0[j]], v01 = f[y0[i] * 16 + x1[j]];
        float v10 = f[y1[i] * 16 + x0[j]], v11 = f[y1[i] * 16 + x1[j]];
        float top = v00 * (1.f - wx[j]) + v01 * wx[j];
        float bot = v10 * (1.f - wx[j]) + v11 * wx[j];
        crops[c * 256 + (i + 1) * 16 + (j + 1)] = top * (1.f - wy[i]) + bot * wy[i];
    }
    __syncthreads();

    // 2x2 maxpool -> g_pooled
    for (int idx = t; idx < FC1_K; idx += 256) {
        int c = idx / 49, p = idx % 49, pi = p / 7, pj = p % 7;
        const float* base = crops + c * 256 + (2 * pi + 1) * 16 + (2 * pj + 1);
        g_pooled[n * FC1_K + idx] = fmaxf(fmaxf(base[0], base[1]), fmaxf(base[16], base[17]));
    }

    // mask conv1: thread = (h = t>>7 [warp-uniform row half], cp = (t>>2)&31, q = t&3)
    int h = t >> 7, cp = (t >> 2) & 31, q = t & 3;
    int qy = q >> 1, qx = q & 1;
    unsigned long long acc[28];
#pragma unroll
    for (int p = 0; p < 28; p++) acc[p] = 0ull;
    const unsigned long long* wrow = g_wpack + cp * 576;
#pragma unroll 1
    for (int ci = 0; ci < 64; ci++) {
        unsigned long long w2[9];
#pragma unroll
        for (int k = 0; k < 9; k++) w2[k] = __ldg(&wrow[ci * 9 + k]);  // L1-resident
        const float* base = crops + ci * 256 + qy * 112 + qx * 7;
        if (h == 0) {
            // output rows i 0..3, input rows r 0..5
#pragma unroll
            for (int r = 0; r < 6; r++) {
                unsigned long long d[9];
#pragma unroll
                for (int c2 = 0; c2 < 9; c2++) d[c2] = dup2(base[r * 16 + c2]);
#pragma unroll
                for (int dy = 0; dy < 3; dy++) {
                    int i = r - dy;
                    if (i >= 0 && i < 4) {
#pragma unroll
                        for (int j = 0; j < 7; j++) {
                            fma2(acc[i * 7 + j], d[j + 0], w2[dy * 3 + 0]);
                            fma2(acc[i * 7 + j], d[j + 1], w2[dy * 3 + 1]);
                            fma2(acc[i * 7 + j], d[j + 2], w2[dy * 3 + 2]);
                        }
                    }
                }
            }
        } else {
            // output rows i 4..6, input rows r 4..8
#pragma unroll
            for (int r = 4; r < 9; r++) {
                unsigned long long d[9];
#pragma unroll
                for (int c2 = 0; c2 < 9; c2++) d[c2] = dup2(base[r * 16 + c2]);
#pragma unroll
                for (int dy = 0; dy < 3; dy++) {
                    int i = r - dy;
                    if (i >= 4 && i < 7) {
#pragma unroll
                        for (int j = 0; j < 7; j++) {
                            fma2(acc[(i - 4) * 7 + j], d[j + 0], w2[dy * 3 + 0]);
                            fma2(acc[(i - 4) * 7 + j], d[j + 1], w2[dy * 3 + 1]);
                            fma2(acc[(i - 4) * 7 + j], d[j + 2], w2[dy * 3 + 2]);
                        }
                    }
                }
            }
        }
    }
    int co0 = 2 * cp;
    float b10 = bm1[co0], b11 = bm1[co0 + 1];
    float w20 = wm2[co0], w21 = wm2[co0 + 1];
    __syncthreads();  // conv + maxpool reads of crops done

    // relu + 1x1 partials into reused crop smem: part[co*196 + q*49 + pp]
    float* part = crops;
    int ibase = h ? 4 : 0, cnt = h ? 21 : 28;
#pragma unroll
    for (int p = 0; p < 28; p++) {
        if (p < cnt) {
            float lo, hi;
            upk2(acc[p], lo, hi);
            int pp = q * 49 + (ibase + p / 7) * 7 + (p % 7);
            part[co0 * 196 + pp] = fmaxf(lo + b10, 0.f) * w20;
            part[(co0 + 1) * 196 + pp] = fmaxf(hi + b11, 0.f) * w21;
        }
    }
    __syncthreads();

    if (t < 196) {
        float s = bm2[0];
#pragma unroll 8
        for (int c = 0; c < 64; c++) s += part[c * 196 + t];
        int qq = t / 49, p2 = t % 49;
        int gi = (qq >> 1) * 7 + p2 / 7, gj = (qq & 1) * 7 + p2 % 7;
        out[OFF_RCNN_MASKS + n * 196 + gi * 14 + gj] = s;
    }
}

// ---------------- tiled GEMM (f32x2, R7 version) ----------------
__global__ void k_gemm(int which, const float* __restrict__ B,
                       const float* __restrict__ bias) {
    const float* A = which ? g_h1 : g_pooled;
    float* C = which ? g_h2 : g_h1;
    const int K = which ? 512 : FC1_K;
    const int M = N_PROP, N = 512;

    __shared__ float As[16][68];
    __shared__ float Bs[16][64];
    int tid = threadIdx.x;
    int m0 = blockIdx.x * 64, n0 = blockIdx.y * 64;
    int ty = tid >> 4, tx = tid & 15;
    unsigned long long acc2[4][2];
#pragma unroll
    for (int i = 0; i < 4; i++) { acc2[i][0] = 0ull; acc2[i][1] = 0ull; }

    int ra = tid >> 2, ca = (tid & 3) * 4;
    int rb = tid >> 4, cb = (tid & 15) * 4;

    for (int k0 = 0; k0 < K; k0 += 16) {
        float4 a4 = make_float4(0.f, 0.f, 0.f, 0.f);
        int m = m0 + ra;
        if (m < M) a4 = *(const float4*)&A[(size_t)m * K + k0 + ca];
        As[ca + 0][ra] = a4.x; As[ca + 1][ra] = a4.y;
        As[ca + 2][ra] = a4.z; As[ca + 3][ra] = a4.w;
        float4 b4 = *(const float4*)&B[(size_t)(k0 + rb) * N + n0 + cb];
        *(float4*)&Bs[rb][cb] = b4;
        __syncthreads();
#pragma unroll
        for (int kk = 0; kk < 16; kk++) {
            float4 av = *(const float4*)&As[kk][ty * 4];
            unsigned long long a0 = dup2(av.x), a1 = dup2(av.y);
            unsigned long long a2 = dup2(av.z), a3 = dup2(av.w);
            unsigned long long b0 = *(const unsigned long long*)&Bs[kk][tx * 4];
            unsigned long long b1 = *(const unsigned long long*)&Bs[kk][tx * 4 + 2];
            fma2(acc2[0][0], a0, b0); fma2(acc2[0][1], a0, b1);
            fma2(acc2[1][0], a1, b0); fma2(acc2[1][1], a1, b1);
            fma2(acc2[2][0], a2, b0); fma2(acc2[2][1], a2, b1);
            fma2(acc2[3][0], a3, b0); fma2(acc2[3][1], a3, b1);
        }
        __syncthreads();
    }
#pragma unroll
    for (int i = 0; i < 4; i++) {
        int m = m0 + ty * 4 + i;
        if (m < M) {
#pragma unroll
            for (int jp = 0; jp < 2; jp++) {
                float lo, hi;
                upk2(acc2[i][jp], lo, hi);
                int nc = n0 + tx * 4 + jp * 2;
                C[(size_t)m * N + nc]     = fmaxf(lo + bias[nc], 0.f);
                C[(size_t)m * N + nc + 1] = fmaxf(hi + bias[nc + 1], 0.f);
            }
        }
    }
}

// ---------------- RCNN heads + decode ----------------
__device__ __forceinline__ float wred(float v) {
#pragma unroll
    for (int o = 16; o; o >>= 1) v += __shfl_xor_sync(0xFFFFFFFFu, v, o);
    return v;
}

__global__ void k_rhead(const float* __restrict__ wrcls, const float* __restrict__ brcls,
                        const float* __restrict__ wrbox, const float* __restrict__ brbox,
                        float* __restrict__ out) {
    int w = threadIdx.x >> 5, lane = threadIdx.x & 31;
    int n = blockIdx.x * 8 + w;
    const float* h = g_h2 + n * 512;
    float p[6];
#pragma unroll
    for (int o = 0; o < 6; o++) p[o] = 0.f;
    for (int k = lane; k < 512; k += 32) {
        float hv = h[k];
        p[0] += hv * wrcls[k * 2 + 0];
        p[1] += hv * wrcls[k * 2 + 1];
        p[2] += hv * wrbox[k * 4 + 0];
        p[3] += hv * wrbox[k * 4 + 1];
        p[4] += hv * wrbox[k * 4 + 2];
        p[5] += hv * wrbox[k * 4 + 3];
    }
#pragma unroll
    for (int o = 0; o < 6; o++) p[o] = wred(p[o]);
    if (lane == 0) {
        float l0 = p[0] + brcls[0], l1 = p[1] + brcls[1];
        float d0 = p[2] + brbox[0], d1 = p[3] + brbox[1];
        float d2 = p[4] + brbox[2], d3 = p[5] + brbox[3];
        out[OFF_RCNN_LOGITS + n * 2 + 0] = l0;
        out[OFF_RCNN_LOGITS + n * 2 + 1] = l1;
        out[OFF_RCNN_DELTAS + n * 4 + 0] = d0;
        out[OFF_RCNN_DELTAS + n * 4 + 1] = d1;
        out[OFF_RCNN_DELTAS + n * 4 + 2] = d2;
        out[OFF_RCNN_DELTAS + n * 4 + 3] = d3;
        float mx = fmaxf(l0, l1);
        float e0 = expf(l0 - mx), e1 = expf(l1 - mx);
        float ds = e1 / (e0 + e1);
        g_dscores[n] = ds;
        float px1 = g_prop[n * 4], py1 = g_prop[n * 4 + 1];
        float px2 = g_prop[n * 4 + 2], py2 = g_prop[n * 4 + 3];
        float pw = px2 - px1, ph = py2 - py1;
        float cx = px1 + 0.5f * pw, cy = py1 + 0.5f * ph;
        float ncx = cx + d0 * pw, ncy = cy + d1 * ph;
        float nw = pw * expf(d2), nh = ph * expf(d3);
        g_dets[n * 4 + 0] = fminf(fmaxf(ncx - 0.5f * nw, 0.f), 255.f);
        g_dets[n * 4 + 1] = fminf(fmaxf(ncy - 0.5f * nh, 0.f), 255.f);
        g_dets[n * 4 + 2] = fminf(fmaxf(ncx + 0.5f * nw, 0.f), 255.f);
        g_dets[n * 4 + 3] = fminf(fmaxf(ncy + 0.5f * nh, 0.f), 255.f);
        g_s2[n] = g_valid[n] ? ds : -1.0f;
    }
}

// ---------------- finalize ----------------
__global__ void k_finalize(float* __restrict__ out) {
    int r = blockIdx.x, t = threadIdx.x;
    int o2 = g_order2[r];
    bool comb = g_keep2[r] && g_valid[o2];
    if (t == 0) {
        out[OFF_KEEP2 + r] = comb ? 1.f : 0.f;
        out[OFF_FINAL_SCORES + r] = comb ? g_dscores[o2] : 0.f;
        out[OFF_FINAL_DETS + r * 4 + 0] = comb ? g_sdets[r * 4 + 0] : 0.f;
        out[OFF_FINAL_DETS + r * 4 + 1] = comb ? g_sdets[r * 4 + 1] : 0.f;
        out[OFF_FINAL_DETS + r * 4 + 2] = comb ? g_sdets[r * 4 + 2] : 0.f;
        out[OFF_FINAL_DETS + r * 4 + 3] = comb ? g_sdets[r * 4 + 3] : 0.f;
    }
    if (t < 196) {
        float m = out[OFF_RCNN_MASKS + o2 * 196 + t];
        out[OFF_FINAL_MASKS + r * 196 + t] = comb ? (1.f / (1.f + expf(-m))) : 0.f;
    }
}

// ---------------- launch ----------------
extern "C" void kernel_launch(void* const* d_in, const int* in_sizes, int n_in,
                              void* d_out, int out_size) {
    const float* x      = (const float*)d_in[0];
    const float* w_bb   = (const float*)d_in[1];
    const float* b_bb   = (const float*)d_in[2];
    const float* w_rpn  = (const float*)d_in[3];
    const float* b_rpn  = (const float*)d_in[4];
    const float* w_cls  = (const float*)d_in[5];
    const float* b_cls  = (const float*)d_in[6];
    const float* w_box  = (const float*)d_in[7];
    const float* b_box  = (const float*)d_in[8];
    const float* w_fc1  = (const float*)d_in[9];
    const float* b_fc1  = (const float*)d_in[10];
    const float* w_fc2  = (const float*)d_in[11];
    const float* b_fc2  = (const float*)d_in[12];
    const float* w_rcls = (const float*)d_in[13];
    const float* b_rcls = (const float*)d_in[14];
    const float* w_rbox = (const float*)d_in[15];
    const float* b_rbox = (const float*)d_in[16];
    const float* w_m1   = (const float*)d_in[17];
    const float* b_m1   = (const float*)d_in[18];
    const float* w_m2   = (const float*)d_in[19];
    const float* b_m2   = (const float*)d_in[20];
    float* out = (float*)d_out;

    cudaFuncSetAttribute(k_roi, cudaFuncAttributeMaxDynamicSharedMemorySize, ROI_SMEM_BYTES);

    k_backbone<<<256, 64>>>(x, w_bb, b_bb);
    k_rpnconv<<<64, 256>>>(w_rpn, b_rpn);
    k_rpnhead<<<256, 64>>>(w_cls, b_cls, w_box, b_box, out);

    k_sort<4096><<<1, 1024>>>(0);
    k_mask<<<36, 1024, NA * 20>>>(0);
    k_scan<<<1, 1024>>>(0, out);

    k_wpack<<<72, 256>>>(w_m1);
    k_roi<<<N_PROP, 256, ROI_SMEM_BYTES>>>(b_m1, w_m2, b_m2, out);
    {
        dim3 g1(32, 8);
        k_gemm<<<g1, 256>>>(0, w_fc1, b_fc1);
        k_gemm<<<g1, 256>>>(1, w_fc2, b_fc2);
    }
    k_rhead<<<250, 256>>>(w_rcls, b_rcls, w_rbox, b_rbox, out);

    k_sort<2048><<<1, 1024>>>(1);
    k_mask<<<32, 1024, N_PROP * 20>>>(1);
    k_scan<<<1, 1024>>>(1, out);

    k_finalize<<<N_PROP, 256>>>(out);
}